// round 2
// baseline (speedup 1.0000x reference)
#include <cuda_runtime.h>
#include <math.h>

// Problem constants
#define BB    64      // batch
#define TT    1024    // timesteps
#define HH    256     // hidden
#define NCTA  128     // persistent CTAs (each owns 2 hidden units, both layers)
#define NT    128     // threads per CTA: tid = u*64 + b  (u in {0,1}, b in [0,64))

// Persistent device state (static allocation only — no cudaMalloc allowed)
__device__ float    g_h0[2][HH * BB];   // [parity][j*64 + b]
__device__ float    g_h1[2][HH * BB];
__device__ float    g_hmean[HH * BB];   // mean over t of h1, [j*64 + b]
__device__ float    g_xT[TT * BB];      // x transposed: [t*64 + b]
__device__ unsigned g_ct;               // global barrier arrive counter (monotonic)

// ---------------------------------------------------------------------------
// Init: reset barrier, zero h state, transpose x to [t][b] for coalesced loads
// ---------------------------------------------------------------------------
__global__ void init_kernel(const float* __restrict__ x) {
    int i = blockIdx.x * blockDim.x + threadIdx.x;
    if (i == 0) g_ct = 0u;
    if (i < TT * BB) {
        int t = i >> 6;         // i / 64
        int b = i & 63;
        g_xT[i] = x[b * TT + t];
    }
    if (i < HH * BB) {
        g_h0[0][i] = 0.f; g_h0[1][i] = 0.f;
        g_h1[0][i] = 0.f; g_h1[1][i] = 0.f;
    }
}

__device__ __forceinline__ float sigmoid_(float x) {
    return 1.f / (1.f + expf(-x));
}

// ---------------------------------------------------------------------------
// Persistent fused 2-layer LSTM recurrence.
// Slot t (t = 0..TT):
//   layer0 computes step t      (active for t < TT)
//   layer1 computes step t-1    (active for t > 0)
// Both only depend on data written before the slot's barrier, so they run
// concurrently inside one barrier interval (1 global barrier per timestep).
//
// CTA bx owns hidden units j = 2*bx + {0,1}. Thread (b,u) computes all 4
// gates for (batch b, unit j) in both layers; c0/c1/hmean-accumulator stay in
// registers for the whole kernel.
// ---------------------------------------------------------------------------
__global__ void __launch_bounds__(NT, 1) lstm_persistent(
    const float* __restrict__ Wh0, const float* __restrict__ Wx0,
    const float* __restrict__ b0,
    const float* __restrict__ Wx1, const float* __restrict__ Wh1,
    const float* __restrict__ b1)
{
    extern __shared__ float smem[];
    float*  sh0 = smem;                         // 16384 f : h0_prev, [k*64+b]
    float*  sh1 = smem + 16384;                 // 16384 f : h1_prev
    float4* sw0 = (float4*)(smem + 32768);          // 512 f4 : Wh0 slice [k][u] -> 4 gates
    float4* swx = (float4*)(smem + 32768 + 2048);   // 512 f4 : Wx1 slice
    float4* sw1 = (float4*)(smem + 32768 + 4096);   // 512 f4 : Wh1 slice

    const int tid = threadIdx.x;
    const int b   = tid & 63;
    const int u   = tid >> 6;
    const int j   = blockIdx.x * 2 + u;

    // Preload this CTA's weight slices into smem (once; gates i,f,g,o at
    // column offsets 0/256/512/768 of the 4H gate vector).
    for (int idx = tid; idx < 512; idx += NT) {
        int k  = idx >> 1;
        int uu = idx & 1;
        int jj = blockIdx.x * 2 + uu;
        const float* r0 = Wh0 + k * 1024;
        sw0[idx] = make_float4(r0[jj], r0[256 + jj], r0[512 + jj], r0[768 + jj]);
        const float* rx = Wx1 + k * 1024;
        swx[idx] = make_float4(rx[jj], rx[256 + jj], rx[512 + jj], rx[768 + jj]);
        const float* r1 = Wh1 + k * 1024;
        sw1[idx] = make_float4(r1[jj], r1[256 + jj], r1[512 + jj], r1[768 + jj]);
    }
    const float4 bia0 = make_float4(b0[j], b0[256 + j], b0[512 + j], b0[768 + j]);
    const float4 bia1 = make_float4(b1[j], b1[256 + j], b1[512 + j], b1[768 + j]);
    const float4 wx0  = make_float4(Wx0[j], Wx0[256 + j], Wx0[512 + j], Wx0[768 + j]);

    float c0 = 0.f, c1 = 0.f, hsum = 0.f;
    __syncthreads();

    for (int t = 0; t <= TT; ++t) {
        if (t > 0) {
            // ---- global barrier #t (monotonic counter; reset by init_kernel) ----
            __threadfence();          // each thread's __stcg of h ordered to L2
            __syncthreads();
            if (tid == 0) {
                atomicAdd(&g_ct, 1u);
                const unsigned target = (unsigned)t * NCTA;
                while (*((volatile unsigned*)&g_ct) < target) { }
            }
            __syncthreads();
        }

        // Stage broadcast h_prev from L2 (L1-bypassing loads: peer-SM writes).
        // layer0[t] and layer1[t-1] both read h0 from parity (t+1)&1;
        // layer1[t-1] reads h1_prev from parity t&1.
        {
            const float4* s0 = (const float4*)g_h0[(t + 1) & 1];
            const float4* s1 = (const float4*)g_h1[t & 1];
            float4* d0 = (float4*)sh0;
            float4* d1 = (float4*)sh1;
            #pragma unroll
            for (int i = 0; i < 32; ++i) {
                const int p = tid + i * NT;
                d0[p] = __ldcg(s0 + p);
                d1[p] = __ldcg(s1 + p);
            }
        }
        __syncthreads();

        // Gate accumulators. layer0 input contribution is an outer product
        // (F_IN = 1): xg0 = x[b,t]*Wx0[:,c] + b0[c].
        const float xv = (t < TT) ? g_xT[t * BB + b] : 0.f;
        float4 a0, a1;
        a0.x = fmaf(xv, wx0.x, bia0.x);
        a0.y = fmaf(xv, wx0.y, bia0.y);
        a0.z = fmaf(xv, wx0.z, bia0.z);
        a0.w = fmaf(xv, wx0.w, bia0.w);
        a1 = bia1;

        const float* ph0 = sh0 + b;
        const float* ph1 = sh1 + b;
        #pragma unroll 8
        for (int k = 0; k < HH; ++k) {
            const float  hv = ph0[k * 64];
            const float4 w0 = sw0[k * 2 + u];          // warp-uniform (broadcast)
            a0.x = fmaf(hv, w0.x, a0.x);
            a0.y = fmaf(hv, w0.y, a0.y);
            a0.z = fmaf(hv, w0.z, a0.z);
            a0.w = fmaf(hv, w0.w, a0.w);
            const float4 wx = swx[k * 2 + u];
            a1.x = fmaf(hv, wx.x, a1.x);
            a1.y = fmaf(hv, wx.y, a1.y);
            a1.z = fmaf(hv, wx.z, a1.z);
            a1.w = fmaf(hv, wx.w, a1.w);
            const float  h1v = ph1[k * 64];
            const float4 w1  = sw1[k * 2 + u];
            a1.x = fmaf(h1v, w1.x, a1.x);
            a1.y = fmaf(h1v, w1.y, a1.y);
            a1.z = fmaf(h1v, w1.z, a1.z);
            a1.w = fmaf(h1v, w1.w, a1.w);
        }

        if (t < TT) {   // layer0 step t
            const float ig = sigmoid_(a0.x);
            const float fg = sigmoid_(a0.y);
            const float gg = tanhf(a0.z);
            const float og = sigmoid_(a0.w);
            c0 = fmaf(fg, c0, ig * gg);
            const float h0n = og * tanhf(c0);
            __stcg(&g_h0[t & 1][j * 64 + b], h0n);
        }
        if (t > 0) {    // layer1 step t-1
            const float ig = sigmoid_(a1.x);
            const float fg = sigmoid_(a1.y);
            const float gg = tanhf(a1.z);
            const float og = sigmoid_(a1.w);
            c1 = fmaf(fg, c1, ig * gg);
            const float h1n = og * tanhf(c1);
            hsum += h1n;
            if (t < TT) __stcg(&g_h1[(t + 1) & 1][j * 64 + b], h1n);
        }
    }

    g_hmean[j * 64 + b] = hsum * (1.f / 1024.f);
}

// ---------------------------------------------------------------------------
// Head: theta projection, concat, 3x (dense + ELU), final dense.
// One CTA per batch row; weights stream from L2 (runs once, tiny).
// ---------------------------------------------------------------------------
__global__ void final_kernel(
    const float* __restrict__ theta,
    const float* __restrict__ pW, const float* __restrict__ pb,
    const float* __restrict__ l0W, const float* __restrict__ l0b,
    const float* __restrict__ l1W, const float* __restrict__ l1b,
    const float* __restrict__ l2W, const float* __restrict__ l2b,
    const float* __restrict__ oW,  const float* __restrict__ ob,
    float* __restrict__ out)
{
    __shared__ float hin[512];
    __shared__ float act0[256];
    __shared__ float act1[256];
    __shared__ float act2[128];
    const int bb = blockIdx.x;
    const int tj = threadIdx.x;

    // concat( mean_t(h1) , theta @ proj_W + proj_b )
    hin[tj] = g_hmean[tj * 64 + bb];
    {
        float s = pb[tj];
        #pragma unroll
        for (int d = 0; d < 5; ++d) s = fmaf(theta[bb * 5 + d], pW[d * 256 + tj], s);
        hin[256 + tj] = s;
    }
    __syncthreads();
    {
        float acc = l0b[tj];
        for (int k = 0; k < 512; ++k) acc = fmaf(hin[k], l0W[k * 256 + tj], acc);
        act0[tj] = acc > 0.f ? acc : expm1f(acc);
    }
    __syncthreads();
    {
        float acc = l1b[tj];
        for (int k = 0; k < 256; ++k) acc = fmaf(act0[k], l1W[k * 256 + tj], acc);
        act1[tj] = acc > 0.f ? acc : expm1f(acc);
    }
    __syncthreads();
    if (tj < 128) {
        float acc = l2b[tj];
        for (int k = 0; k < 256; ++k) acc = fmaf(act1[k], l2W[k * 128 + tj], acc);
        act2[tj] = acc > 0.f ? acc : expm1f(acc);
    }
    __syncthreads();
    if (tj == 0) {
        float s = ob[0];
        for (int k = 0; k < 128; ++k) s = fmaf(act2[k], oW[k], s);
        out[bb] = s;
    }
}

// ---------------------------------------------------------------------------
extern "C" void kernel_launch(void* const* d_in, const int* in_sizes, int n_in,
                              void* d_out, int out_size) {
    const float* x     = (const float*)d_in[0];
    const float* theta = (const float*)d_in[1];
    const float* Wx0   = (const float*)d_in[2];
    const float* Wh0   = (const float*)d_in[3];
    const float* b0    = (const float*)d_in[4];
    const float* Wx1   = (const float*)d_in[5];
    const float* Wh1   = (const float*)d_in[6];
    const float* b1    = (const float*)d_in[7];
    const float* pW    = (const float*)d_in[8];
    const float* pb    = (const float*)d_in[9];
    const float* l0W   = (const float*)d_in[10];
    const float* l0b   = (const float*)d_in[11];
    const float* l1W   = (const float*)d_in[12];
    const float* l1b   = (const float*)d_in[13];
    const float* l2W   = (const float*)d_in[14];
    const float* l2b   = (const float*)d_in[15];
    const float* oW    = (const float*)d_in[16];
    const float* ob    = (const float*)d_in[17];

    // 152 KB dynamic smem (h0 + h1 stage + 3 weight slices)
    const int smem_bytes = (16384 + 16384 + 3 * 2048) * (int)sizeof(float);
    cudaFuncSetAttribute(lstm_persistent,
                         cudaFuncAttributeMaxDynamicSharedMemorySize, smem_bytes);

    init_kernel<<<(TT * BB + 255) / 256, 256>>>(x);
    lstm_persistent<<<NCTA, NT, smem_bytes>>>(Wh0, Wx0, b0, Wx1, Wh1, b1);
    final_kernel<<<BB, 256>>>(theta, pW, pb, l0W, l0b, l1W, l1b,
                              l2W, l2b, oW, ob, (float*)d_out);
}

// round 4
// speedup vs baseline: 1.1972x; 1.1972x over previous
#include <cuda_runtime.h>
#include <math.h>
#include <stdint.h>

// Problem constants
#define BB    64      // batch
#define TT    1024    // timesteps
#define HH    256     // hidden
#define NCTA  128     // persistent CTAs (each owns 2 hidden units, both layers)
#define NT    128     // threads: tid = u*64 + b

#define M_TOT        128     // k-pairs (HH/2)
#define NCHUNK       4
#define M_PER_CHUNK  32
#define CHUNK_FLOATS 4096    // per h-array per chunk
#define CHUNK_BYTES  16384

typedef unsigned long long ull;

// Persistent device state (static allocation only)
// h layout: [pair m][batch b][e]  ->  idx = m*128 + b*2 + e,  unit k = 2m+e
__device__ __align__(128) float g_h0[2][HH * BB];
__device__ __align__(128) float g_h1[2][HH * BB];
__device__ float    g_hmean[HH * BB];   // [j*64 + b]
__device__ float    g_xT[TT * BB];      // [t*64 + b]
__device__ unsigned g_ct;               // global barrier counter (monotonic)

// ---------------------------------------------------------------------------
__global__ void init_kernel(const float* __restrict__ x) {
    int i = blockIdx.x * blockDim.x + threadIdx.x;
    if (i == 0) g_ct = 0u;
    if (i < TT * BB) {
        int t = i >> 6;
        int b = i & 63;
        g_xT[i] = x[b * TT + t];
    }
    if (i < HH * BB) {
        g_h0[0][i] = 0.f; g_h0[1][i] = 0.f;
        g_h1[0][i] = 0.f; g_h1[1][i] = 0.f;
    }
}

// ---------------------------------------------------------------------------
// helpers
// ---------------------------------------------------------------------------
__device__ __forceinline__ uint32_t smem_u32(const void* p) {
    uint32_t a;
    asm("{ .reg .u64 t; cvta.to.shared.u64 t, %1; cvt.u32.u64 %0, t; }"
        : "=r"(a) : "l"(p));
    return a;
}

__device__ __forceinline__ void fma2(ull& d, ull a, ull b) {
    asm("fma.rn.f32x2 %0, %1, %2, %0;" : "+l"(d) : "l"(a), "l"(b));
}

__device__ __forceinline__ ull pack2(float lo, float hi) {
    ull v; asm("mov.b64 %0, {%1, %2};" : "=l"(v) : "f"(lo), "f"(hi)); return v;
}

__device__ __forceinline__ float hadd2(ull v) {
    float lo, hi; asm("mov.b64 {%0, %1}, %2;" : "=f"(lo), "=f"(hi) : "l"(v));
    return lo + hi;
}

__device__ __forceinline__ void mbar_init(uint32_t a, unsigned cnt) {
    asm volatile("mbarrier.init.shared.b64 [%0], %1;" :: "r"(a), "r"(cnt) : "memory");
}

__device__ __forceinline__ void mbar_expect_tx(uint32_t a, unsigned bytes) {
    asm volatile("mbarrier.arrive.expect_tx.shared.b64 _, [%0], %1;"
                 :: "r"(a), "r"(bytes) : "memory");
}

__device__ __forceinline__ void mbar_wait(uint32_t a, unsigned parity) {
    asm volatile(
        "{\n\t.reg .pred P;\n\t"
        "WL%=:\n\t"
        "mbarrier.try_wait.parity.acquire.cta.shared::cta.b64 P, [%0], %1, 0x989680;\n\t"
        "@P bra.uni WD%=;\n\t"
        "bra.uni WL%=;\n\t"
        "WD%=:\n\t}"
        :: "r"(a), "r"(parity) : "memory");
}

__device__ __forceinline__ void bulk_g2s(uint32_t dst, const void* src,
                                         unsigned bytes, uint32_t mbar) {
    asm volatile(
        "cp.async.bulk.shared::cluster.global.mbarrier::complete_tx::bytes "
        "[%0], [%1], %2, [%3];"
        :: "r"(dst), "l"(src), "r"(bytes), "r"(mbar) : "memory");
}

__device__ __forceinline__ float sigm(float x) {
    return __fdividef(1.f, 1.f + __expf(-x));
}
__device__ __forceinline__ float tanh_f(float x) {
    float e = __expf(-2.f * fabsf(x));
    float t = __fdividef(1.f - e, 1.f + e);
    return copysignf(t, x);
}

// ---------------------------------------------------------------------------
// Persistent fused 2-layer LSTM.
// Slot t: layer0 computes step t (t<TT); layer1 computes step t-1 (t>0).
// One global barrier per slot. Per slot, thread 0 issues 4 chunked
// cp.async.bulk copies of h0_prev/h1_prev; compute on chunk c overlaps
// arrival of chunks c+1..  Gate reduction is packed f32x2 along k-pairs.
// ---------------------------------------------------------------------------
__global__ void __launch_bounds__(NT, 1) lstm_persistent(
    const float* __restrict__ Wh0, const float* __restrict__ Wx0,
    const float* __restrict__ b0,
    const float* __restrict__ Wx1, const float* __restrict__ Wh1,
    const float* __restrict__ b1)
{
    extern __shared__ float smem[];
    // layout (floats): sh0[16384] | sh1[16384] | w0[2048] | wx[2048] | w1[2048] | mbars
    float* sh0 = smem;
    float* sh1 = smem + 16384;
    float* w0s = smem + 32768;
    float* wxs = smem + 34816;
    float* w1s = smem + 36864;

    const uint32_t sbase   = smem_u32(smem);
    const uint32_t sh1_u32 = sbase + 65536;
    const uint32_t mbar_u  = sbase + 155648;

    const int tid = threadIdx.x;
    const int b   = tid & 63;
    const int u   = tid >> 6;
    const int j   = blockIdx.x * 2 + u;

    if (tid == 0) {
        #pragma unroll
        for (int c = 0; c < NCHUNK; ++c) mbar_init(mbar_u + c * 8, 1);
    }

    // Preload weight slices as k-pair float2 per gate:
    // w[(m*2+u)*4 + g] = { W[2m][g*256+j], W[2m+1][g*256+j] }
    for (int idx = tid; idx < 256; idx += NT) {
        const int m  = idx >> 1;
        const int uu = idx & 1;
        const int jj = blockIdx.x * 2 + uu;
        float2* d0 = (float2*)w0s + idx * 4;
        float2* dx = (float2*)wxs + idx * 4;
        float2* d1 = (float2*)w1s + idx * 4;
        const float* ra0 = Wh0 + (2 * m) * 1024;
        const float* rb0 = Wh0 + (2 * m + 1) * 1024;
        const float* rax = Wx1 + (2 * m) * 1024;
        const float* rbx = Wx1 + (2 * m + 1) * 1024;
        const float* ra1 = Wh1 + (2 * m) * 1024;
        const float* rb1 = Wh1 + (2 * m + 1) * 1024;
        #pragma unroll
        for (int g = 0; g < 4; ++g) {
            d0[g] = make_float2(ra0[g * 256 + jj], rb0[g * 256 + jj]);
            dx[g] = make_float2(rax[g * 256 + jj], rbx[g * 256 + jj]);
            d1[g] = make_float2(ra1[g * 256 + jj], rb1[g * 256 + jj]);
        }
    }
    const float4 bia0 = make_float4(b0[j], b0[256 + j], b0[512 + j], b0[768 + j]);
    const float4 bia1 = make_float4(b1[j], b1[256 + j], b1[512 + j], b1[768 + j]);
    const float4 wx0  = make_float4(Wx0[j], Wx0[256 + j], Wx0[512 + j], Wx0[768 + j]);

    float c0 = 0.f, c1 = 0.f, hsum = 0.f;
    __syncthreads();   // mbar init + weights visible

    // per-thread pointers for the inner loop
    const ull* ph0 = (const ull*)sh0 + b;             // hv2  at ph0[m*64]
    const ull* ph1 = (const ull*)sh1 + b;             // h1v2 at ph1[m*64]
    const ulonglong2* pw0 = (const ulonglong2*)w0s + u * 2;   // [m*4], [m*4+1]
    const ulonglong2* pwx = (const ulonglong2*)wxs + u * 2;
    const ulonglong2* pw1 = (const ulonglong2*)w1s + u * 2;

    const int houti = (j >> 1) * 128 + b * 2 + (j & 1);

    for (int t = 0; t <= TT; ++t) {
        if (t > 0) {
            __threadfence();      // own h stores -> L2
            __syncthreads();      // whole CTA done with previous slot
            if (tid == 0) {
                atomicAdd(&g_ct, 1u);                 // emitted as RED (result unused)
                const unsigned target = (unsigned)t * NCTA;
                while (*((volatile unsigned*)&g_ct) < target) { }
            }
            // NOTE: no __syncthreads here — other threads run ahead to the
            // mbar waits, which gate on this slot's TMA completions.
        }

        if (tid == 0) {
            asm volatile("fence.proxy.async;" ::: "memory");
            const float* s0 = g_h0[(t + 1) & 1];
            const float* s1 = g_h1[t & 1];
            #pragma unroll
            for (int c = 0; c < NCHUNK; ++c) {
                const uint32_t mb = mbar_u + c * 8;
                mbar_expect_tx(mb, 2 * CHUNK_BYTES);
                bulk_g2s(sbase   + c * CHUNK_BYTES, s0 + c * CHUNK_FLOATS, CHUNK_BYTES, mb);
                bulk_g2s(sh1_u32 + c * CHUNK_BYTES, s1 + c * CHUNK_FLOATS, CHUNK_BYTES, mb);
            }
        }

        // init gate accumulators (lane-lo gets bias + x-contribution)
        const float xv = (t < TT) ? g_xT[t * BB + b] : 0.f;
        ull a0i = pack2(fmaf(xv, wx0.x, bia0.x), 0.f);
        ull a0f = pack2(fmaf(xv, wx0.y, bia0.y), 0.f);
        ull a0g = pack2(fmaf(xv, wx0.z, bia0.z), 0.f);
        ull a0o = pack2(fmaf(xv, wx0.w, bia0.w), 0.f);
        ull a1i = pack2(bia1.x, 0.f);
        ull a1f = pack2(bia1.y, 0.f);
        ull a1g = pack2(bia1.z, 0.f);
        ull a1o = pack2(bia1.w, 0.f);

        const unsigned par = (unsigned)(t & 1);
        #pragma unroll
        for (int c = 0; c < NCHUNK; ++c) {
            mbar_wait(mbar_u + c * 8, par);
            const int mbase = c * M_PER_CHUNK;
            #pragma unroll 8
            for (int mm = 0; mm < M_PER_CHUNK; ++mm) {
                const int m = mbase + mm;
                const ull hv2  = ph0[m * 64];
                const ull h1v2 = ph1[m * 64];
                const ulonglong2 w0a = pw0[m * 4];
                const ulonglong2 w0b = pw0[m * 4 + 1];
                fma2(a0i, hv2, w0a.x); fma2(a0f, hv2, w0a.y);
                fma2(a0g, hv2, w0b.x); fma2(a0o, hv2, w0b.y);
                const ulonglong2 wxa = pwx[m * 4];
                const ulonglong2 wxb = pwx[m * 4 + 1];
                fma2(a1i, hv2, wxa.x); fma2(a1f, hv2, wxa.y);
                fma2(a1g, hv2, wxb.x); fma2(a1o, hv2, wxb.y);
                const ulonglong2 w1a = pw1[m * 4];
                const ulonglong2 w1b = pw1[m * 4 + 1];
                fma2(a1i, h1v2, w1a.x); fma2(a1f, h1v2, w1a.y);
                fma2(a1g, h1v2, w1b.x); fma2(a1o, h1v2, w1b.y);
            }
        }

        if (t < TT) {   // layer0 step t
            const float ig = sigm(hadd2(a0i));
            const float fg = sigm(hadd2(a0f));
            const float gg = tanh_f(hadd2(a0g));
            const float og = sigm(hadd2(a0o));
            c0 = fmaf(fg, c0, ig * gg);
            const float h0n = og * tanh_f(c0);
            __stcg(&g_h0[t & 1][houti], h0n);
        }
        if (t > 0) {    // layer1 step t-1
            const float ig = sigm(hadd2(a1i));
            const float fg = sigm(hadd2(a1f));
            const float gg = tanh_f(hadd2(a1g));
            const float og = sigm(hadd2(a1o));
            c1 = fmaf(fg, c1, ig * gg);
            const float h1n = og * tanh_f(c1);
            hsum += h1n;
            if (t < TT) __stcg(&g_h1[(t + 1) & 1][houti], h1n);
        }
    }

    g_hmean[j * 64 + b] = hsum * (1.f / 1024.f);
}

// ---------------------------------------------------------------------------
// Head: theta projection, concat, 3x (dense + ELU), final dense. Runs once.
// ---------------------------------------------------------------------------
__global__ void final_kernel(
    const float* __restrict__ theta,
    const float* __restrict__ pW, const float* __restrict__ pb,
    const float* __restrict__ l0W, const float* __restrict__ l0b,
    const float* __restrict__ l1W, const float* __restrict__ l1b,
    const float* __restrict__ l2W, const float* __restrict__ l2b,
    const float* __restrict__ oW,  const float* __restrict__ ob,
    float* __restrict__ out)
{
    __shared__ float hin[512];
    __shared__ float act0[256];
    __shared__ float act1[256];
    __shared__ float act2[128];
    const int bb = blockIdx.x;
    const int tj = threadIdx.x;

    hin[tj] = g_hmean[tj * 64 + bb];
    {
        float s = pb[tj];
        #pragma unroll
        for (int d = 0; d < 5; ++d) s = fmaf(theta[bb * 5 + d], pW[d * 256 + tj], s);
        hin[256 + tj] = s;
    }
    __syncthreads();
    {
        float acc = l0b[tj];
        for (int k = 0; k < 512; ++k) acc = fmaf(hin[k], l0W[k * 256 + tj], acc);
        act0[tj] = acc > 0.f ? acc : expm1f(acc);
    }
    __syncthreads();
    {
        float acc = l1b[tj];
        for (int k = 0; k < 256; ++k) acc = fmaf(act0[k], l1W[k * 256 + tj], acc);
        act1[tj] = acc > 0.f ? acc : expm1f(acc);
    }
    __syncthreads();
    if (tj < 128) {
        float acc = l2b[tj];
        for (int k = 0; k < 256; ++k) acc = fmaf(act1[k], l2W[k * 128 + tj], acc);
        act2[tj] = acc > 0.f ? acc : expm1f(acc);
    }
    __syncthreads();
    if (tj == 0) {
        float s = ob[0];
        for (int k = 0; k < 128; ++k) s = fmaf(act2[k], oW[k], s);
        out[bb] = s;
    }
}

// ---------------------------------------------------------------------------
extern "C" void kernel_launch(void* const* d_in, const int* in_sizes, int n_in,
                              void* d_out, int out_size) {
    const float* x     = (const float*)d_in[0];
    const float* theta = (const float*)d_in[1];
    const float* Wx0   = (const float*)d_in[2];
    const float* Wh0   = (const float*)d_in[3];
    const float* b0    = (const float*)d_in[4];
    const float* Wx1   = (const float*)d_in[5];
    const float* Wh1   = (const float*)d_in[6];
    const float* b1    = (const float*)d_in[7];
    const float* pW    = (const float*)d_in[8];
    const float* pb    = (const float*)d_in[9];
    const float* l0W   = (const float*)d_in[10];
    const float* l0b   = (const float*)d_in[11];
    const float* l1W   = (const float*)d_in[12];
    const float* l1b   = (const float*)d_in[13];
    const float* l2W   = (const float*)d_in[14];
    const float* l2b   = (const float*)d_in[15];
    const float* oW    = (const float*)d_in[16];
    const float* ob    = (const float*)d_in[17];

    // 64K + 64K + 3*8K floats + mbars = 155648 + 64 bytes
    const int smem_bytes = 155712;
    cudaFuncSetAttribute(lstm_persistent,
                         cudaFuncAttributeMaxDynamicSharedMemorySize, smem_bytes);

    init_kernel<<<(TT * BB + 255) / 256, 256>>>(x);
    lstm_persistent<<<NCTA, NT, smem_bytes>>>(Wh0, Wx0, b0, Wx1, Wh1, b1);
    final_kernel<<<BB, 256>>>(theta, pW, pb, l0W, l0b, l1W, l1b,
                              l2W, l2b, oW, ob, (float*)d_out);
}